// round 8
// baseline (speedup 1.0000x reference)
#include <cuda_runtime.h>

// Problem constants (z: (4,64,16,32,32) f32, emb: (1024,64) f32)
#define NBATCH 4
#define NC     64
#define SP     16384            // 16*32*32 spatial per batch
#define NROWS  (NBATCH * SP)    // 65536
#define KCODES 1024
#define TK     64               // codebook tile (smem buffer granularity)
#define NZQ    (NBATCH * NC * SP)  // 4194304
#define BLK    128
#define ROWS_PER_CHUNK BLK                  // 128 (1 row/thread)
#define NCHUNKS (NROWS / ROWS_PER_CHUNK)    // 512
#define NSLICE 8
#define CPS    (KCODES / NSLICE)            // 128 codes per slice
#define NITEMS (NCHUNKS * NSLICE)           // 4096
#define GRID_SWEEP 592                      // 148 SMs * 4 target blocks
#define NBLK_EPI (NROWS / BLK)              // 512

__device__ float  g_e2[KCODES];
__device__ float  g_sc[NSLICE][NROWS];   // per-slice best score
__device__ int    g_bk[NSLICE][NROWS];   // per-slice best index
__device__ double g_partial[NBLK_EPI];
__device__ unsigned g_item = 0;

// ---------------------------------------------------------------------------
// cp.async helpers
// ---------------------------------------------------------------------------
__device__ __forceinline__ void cp_async16(unsigned smem_addr, const void* gptr) {
    asm volatile("cp.async.cg.shared.global [%0], [%1], 16;\n"
                 :: "r"(smem_addr), "l"(gptr));
}
__device__ __forceinline__ void cp_commit() {
    asm volatile("cp.async.commit_group;\n");
}
template <int N>
__device__ __forceinline__ void cp_wait() {
    asm volatile("cp.async.wait_group %0;\n" :: "n"(N));
}

#define FMA2(acc, x, y) \
    asm("fma.rn.f32x2 %0, %1, %2, %0;" : "+l"(acc) : "l"(x), "l"(y))
#define ADD2(a, b) \
    asm("add.rn.f32x2 %0, %0, %1;" : "+l"(a) : "l"(b))

// ---------------------------------------------------------------------------
// Kernel 1: per-code squared norms (IDENTICAL contraction to round 1)
// ---------------------------------------------------------------------------
__global__ void prep_kernel(const float* __restrict__ emb) {
    int k = blockIdx.x * blockDim.x + threadIdx.x;
    if (k < KCODES) {
        const float4* e = (const float4*)(emb + k * NC);
        float s = 0.f;
#pragma unroll
        for (int i = 0; i < NC / 4; i++) {
            float4 v = e[i];
            s += v.x * v.x + v.y * v.y + v.z * v.z + v.w * v.w;
        }
        g_e2[k] = s;
    }
}

// ---------------------------------------------------------------------------
// Kernel 2: persistent sweep — dynamic queue of (chunk, k-slice) items.
// 1 row/thread, 2 codes per inner iteration, frozen score numerics.
// ---------------------------------------------------------------------------
__global__ void __launch_bounds__(BLK, 4)
sweep_kernel(const float* __restrict__ z, const float* __restrict__ emb) {
    __shared__ __align__(16) float se[2][TK * NC];   // 2 x 16 KB codebook tiles
    __shared__ __align__(16) float e2h[CPS];         // this slice's norms
    __shared__ unsigned s_item;

    const int tid = threadIdx.x;

    for (;;) {
        __syncthreads();   // barrier A: smem safe for reuse, s_item consumed
        if (tid == 0) s_item = atomicAdd(&g_item, 1u);
        __syncthreads();   // barrier B: s_item visible
        const unsigned it = s_item;
        if (it >= NITEMS) break;

        const int chunk = it >> 3;
        const int slice = it & (NSLICE - 1);
        const int kbase = slice * CPS;
        const float* embs = emb + (size_t)kbase * NC;

        // Issue both tiles of this slice (group0 = tile0 + e2, group1 = tile1)
#pragma unroll
        for (int t = 0; t < 2; t++) {
            unsigned sb = (unsigned)__cvta_generic_to_shared(&se[t][0]);
            const char* gb = (const char*)(embs + (size_t)t * TK * NC);
#pragma unroll
            for (int j = 0; j < (TK * NC * 4) / (BLK * 16); j++)
                cp_async16(sb + (tid + j * BLK) * 16, gb + (tid + j * BLK) * 16);
            if (t == 0 && tid < CPS / 4)
                cp_async16((unsigned)__cvta_generic_to_shared(&e2h[tid * 4]),
                           &g_e2[kbase + tid * 4]);
            cp_commit();
        }

        const int row = chunk * ROWS_PER_CHUNK + tid;
        const int b = row >> 14;
        const int s = row & (SP - 1);
        const float* zp = z + (size_t)b * NC * SP + s;

        // Load this row's z (coalesced) + frozen pairwise z2 + pack to f32x2
        unsigned long long zr[NC / 2];
        float z2;
        {
            float zv[NC];
#pragma unroll
            for (int c = 0; c < NC; c++) zv[c] = zp[(size_t)c * SP];
            float t32[32];
#pragma unroll
            for (int i = 0; i < 32; i++)
                t32[i] = __fadd_rn(__fmul_rn(zv[2 * i], zv[2 * i]),
                                   __fmul_rn(zv[2 * i + 1], zv[2 * i + 1]));
#pragma unroll
            for (int st = 16; st >= 1; st >>= 1)
#pragma unroll
                for (int i = 0; i < 16; i++)
                    if (i < st) t32[i] = __fadd_rn(t32[i], t32[i + st]);
            z2 = t32[0];
#pragma unroll
            for (int j = 0; j < NC / 2; j++)
                asm("mov.b64 %0, {%1, %2};" : "=l"(zr[j]) : "f"(zv[2 * j]), "f"(zv[2 * j + 1]));
        }

        float best = __int_as_float(0x7f800000);
        int bk = kbase;

#pragma unroll
        for (int t = 0; t < 2; t++) {
            if (t == 0) cp_wait<1>(); else cp_wait<0>();
            __syncthreads();
            const int k0 = kbase + t * TK;

#pragma unroll 2
            for (int kk = 0; kk < TK; kk += 2) {
                const ulonglong2* ep0 = (const ulonglong2*)(&se[t][kk * NC]);
                const ulonglong2* ep1 = (const ulonglong2*)(&se[t][(kk + 1) * NC]);
                unsigned long long a0 = 0ull, a1 = 0ull, a2 = 0ull, a3 = 0ull;
                unsigned long long c0 = 0ull, c1 = 0ull, c2 = 0ull, c3 = 0ull;
#pragma unroll
                for (int i = 0; i < 8; i++) {
                    ulonglong2 ea01 = ep0[2 * i];
                    ulonglong2 ea23 = ep0[2 * i + 1];
                    ulonglong2 eb01 = ep1[2 * i];
                    ulonglong2 eb23 = ep1[2 * i + 1];
                    FMA2(a0, zr[4 * i + 0], ea01.x);
                    FMA2(a1, zr[4 * i + 1], ea01.y);
                    FMA2(a2, zr[4 * i + 2], ea23.x);
                    FMA2(a3, zr[4 * i + 3], ea23.y);
                    FMA2(c0, zr[4 * i + 0], eb01.x);
                    FMA2(c1, zr[4 * i + 1], eb01.y);
                    FMA2(c2, zr[4 * i + 2], eb23.x);
                    FMA2(c3, zr[4 * i + 3], eb23.y);
                }
                const float e2a = e2h[t * TK + kk];
                const float e2b = e2h[t * TK + kk + 1];
                // Code kk tail (frozen op order; FFMA(-2) == fl(t - fl(2*dot))
                // because 2*dot is exact in fp32)
                ADD2(a0, a1); ADD2(a2, a3); ADD2(a0, a2);
                float lo, hi;
                asm("mov.b64 {%0, %1}, %2;" : "=f"(lo), "=f"(hi) : "l"(a0));
                const float dot0 = __fadd_rn(lo, hi);
                const float sc0 = __fmaf_rn(dot0, -2.0f, __fadd_rn(z2, e2a));
                if (sc0 < best) { best = sc0; bk = k0 + kk; }
                // Code kk+1 tail
                ADD2(c0, c1); ADD2(c2, c3); ADD2(c0, c2);
                asm("mov.b64 {%0, %1}, %2;" : "=f"(lo), "=f"(hi) : "l"(c0));
                const float dot1 = __fadd_rn(lo, hi);
                const float sc1 = __fmaf_rn(dot1, -2.0f, __fadd_rn(z2, e2b));
                if (sc1 < best) { best = sc1; bk = k0 + kk + 1; }
            }
        }

        g_sc[slice][row] = best;
        g_bk[slice][row] = bk;
    }
}

// ---------------------------------------------------------------------------
// Kernel 3: merge slices + STE epilogue + loss partials (1 row/thread).
// Ascending-slice scan with strict < == global ascending-k first-min.
// ---------------------------------------------------------------------------
__global__ void __launch_bounds__(BLK)
epi_kernel(const float* __restrict__ z, const float* __restrict__ emb,
           float* __restrict__ out, int write_idx) {
    __shared__ float wsum[BLK / 32];
    const int tid = threadIdx.x;
    const int row = blockIdx.x * BLK + tid;
    const int b = row >> 14;
    const int s = row & (SP - 1);

    float best = g_sc[0][row];
    int bk = g_bk[0][row];
#pragma unroll
    for (int sl = 1; sl < NSLICE; sl++) {
        const float scs = g_sc[sl][row];
        if (scs < best) { best = scs; bk = g_bk[sl][row]; }
    }

    const float* zp = z + (size_t)b * NC * SP + s;
    const float4* eb4 = (const float4*)(emb + (size_t)bk * NC);
    float* oz = out + (size_t)b * NC * SP + s;

    float lsum = 0.f;
#pragma unroll
    for (int i = 0; i < NC / 4; i++) {
        float4 e = eb4[i];
        float zq0 = zp[(size_t)(4 * i + 0) * SP];
        float zq1 = zp[(size_t)(4 * i + 1) * SP];
        float zq2 = zp[(size_t)(4 * i + 2) * SP];
        float zq3 = zp[(size_t)(4 * i + 3) * SP];
        // Frozen STE numerics: q = zc + (e - zc)
        float q0 = __fadd_rn(zq0, __fsub_rn(e.x, zq0));
        float q1 = __fadd_rn(zq1, __fsub_rn(e.y, zq1));
        float q2 = __fadd_rn(zq2, __fsub_rn(e.z, zq2));
        float q3 = __fadd_rn(zq3, __fsub_rn(e.w, zq3));
        float d0 = __fsub_rn(q0, zq0);
        float d1 = __fsub_rn(q1, zq1);
        float d2 = __fsub_rn(q2, zq2);
        float d3 = __fsub_rn(q3, zq3);
        lsum += d0 * d0 + d1 * d1 + d2 * d2 + d3 * d3;
        oz[(size_t)(4 * i + 0) * SP] = q0;
        oz[(size_t)(4 * i + 1) * SP] = q1;
        oz[(size_t)(4 * i + 2) * SP] = q2;
        oz[(size_t)(4 * i + 3) * SP] = q3;
    }

    if (write_idx) out[(size_t)NZQ + 1 + row] = (float)bk;

    // Deterministic block reduction of the loss partial
    const int lane = tid & 31;
    const int wrp = tid >> 5;
#pragma unroll
    for (int off = 16; off; off >>= 1)
        lsum += __shfl_down_sync(0xffffffffu, lsum, off);
    if (lane == 0) wsum[wrp] = lsum;
    __syncthreads();
    if (tid == 0) {
        double sd = 0.0;
#pragma unroll
        for (int w = 0; w < BLK / 32; w++) sd += (double)wsum[w];
        g_partial[blockIdx.x] = sd;
    }
}

// ---------------------------------------------------------------------------
// Kernel 4: deterministic final loss reduction + work-queue reset
// ---------------------------------------------------------------------------
__global__ void fin_kernel(float* __restrict__ out, int write_loss) {
    __shared__ double sd[256];
    int t = threadIdx.x;
    double s = 0.0;
#pragma unroll
    for (int i = 0; i < NBLK_EPI / 256; i++) s += g_partial[t + i * 256];
    sd[t] = s;
    __syncthreads();
    for (int st = 128; st >= 1; st >>= 1) {
        if (t < st) sd[t] += sd[t + st];
        __syncthreads();
    }
    if (t == 0) {
        if (write_loss)
            out[NZQ] = (float)(1.25 * sd[0] / (double)NZQ);
        g_item = 0;   // reset the work queue for the next graph replay
    }
}

// ---------------------------------------------------------------------------
extern "C" void kernel_launch(void* const* d_in, const int* in_sizes, int n_in,
                              void* d_out, int out_size) {
    const float* z = (const float*)d_in[0];
    const float* emb = (const float*)d_in[1];
    // Defensive: identify tensors by element count (z: 4194304, emb: 65536)
    if (n_in >= 2 && in_sizes[0] == KCODES * NC && in_sizes[1] == NZQ) {
        const float* tmp = z; z = emb; emb = tmp;
    }
    float* out = (float*)d_out;
    const int write_loss = (out_size >= NZQ + 1) ? 1 : 0;
    const int write_idx = (out_size >= NZQ + 1 + NROWS) ? 1 : 0;

    prep_kernel<<<(KCODES + 127) / 128, 128>>>(emb);
    sweep_kernel<<<GRID_SWEEP, BLK>>>(z, emb);
    epi_kernel<<<NBLK_EPI, BLK>>>(z, emb, out, write_idx);
    fin_kernel<<<1, 256>>>(out, write_loss);
}